// round 14
// baseline (speedup 1.0000x reference)
#include <cuda_runtime.h>
#include <cuda_fp16.h>
#include <cstdint>

// ============================================================================
// EdgeUpdate: out[e] = relu( concat(nf[src[e]]+nf[dst[e]], ef[e]) @ W^T + b )
// GEMM: M=E (640000), N=128, K=256. fp16 mma.m16n8k16, fp32 accumulate.
//
// R14 = R13 with the scratch-stride alignment bug fixed (33 -> 32 words).
// Warp-private smem-bounce epilogue: fragment STS.64 into a rotated layout
//   word(r, chunk, u) = r*32 + 4*((chunk + r)&7) + u   (chunk logical 0..7)
// then LDS.128 whole rows (phase = all 32 banks) + STG.128 full lines.
// Rotation (not padding) provides conflict-freedom; stride 32 keeps 16B
// alignment for LDS.128. Pipeline / layouts / MMA identical to R12 (238us).
// ============================================================================

static constexpr int SMB_BIAS = 0;
static constexpr int SMB_W    = 512;                  // 64 KB
static constexpr int SMB_A    = 512 + 65536;          // 4 groups x 4 x 4096
static constexpr int SMB_SCR  = SMB_A + 65536;        // 16 warps x 4096
static constexpr int SM_BYTES = SMB_SCR + 16 * 4096;  // 197120

__device__ __forceinline__ void mma_f16(float* d, uint32_t a0, uint32_t a1,
                                        uint32_t a2, uint32_t a3,
                                        uint32_t b0, uint32_t b1) {
    asm volatile(
        "mma.sync.aligned.m16n8k16.row.col.f32.f16.f16.f32 "
        "{%0,%1,%2,%3}, {%4,%5,%6,%7}, {%8,%9}, {%0,%1,%2,%3};"
        : "+f"(d[0]), "+f"(d[1]), "+f"(d[2]), "+f"(d[3])
        : "r"(a0), "r"(a1), "r"(a2), "r"(a3), "r"(b0), "r"(b1));
}

__device__ __forceinline__ uint32_t h2(float lo, float hi) {
    __half2 v = __floats2half2_rn(lo, hi);
    return *reinterpret_cast<uint32_t*>(&v);
}

__global__ void __launch_bounds__(512, 1)
edge_update_kernel(const float* __restrict__ nf,
                   const int* __restrict__ ei,      // int32[2*E] (JAX x64 off)
                   const float* __restrict__ ef,
                   const float* __restrict__ W,
                   const float* __restrict__ bias,
                   float* __restrict__ out, int E) {
    extern __shared__ char smem[];
    float* bsm = (float*)(smem + SMB_BIAS);

    const int tid = threadIdx.x;
    const int wid = tid >> 5;
    const int lid = tid & 31;
    const int g   = lid >> 2;          // 0..7
    const int t   = lid & 3;           // 0..3
    const int gid = wid >> 2;          // group 0..3
    const int w4  = wid & 3;           // warp in group = N strip
    const int nw  = w4 * 32;

    if (tid < 128) bsm[tid] = bias[tid];

    // ---- One-time: W -> packed fp16 smem ----
    for (int task = tid; task < 1024; task += 512) {
        const int c = task >> 3, p = task & 7;
        const float* src = W + c * 256 + p * 32;
        float x[32];
#pragma unroll
        for (int i = 0; i < 8; i++) {
            float4 v = ((const float4*)src)[i];
            x[4 * i] = v.x; x[4 * i + 1] = v.y;
            x[4 * i + 2] = v.z; x[4 * i + 3] = v.w;
        }
        char* base = smem + SMB_W + (c >> 3) * 4096 + p * 512 + (c & 7) * 64;
#pragma unroll
        for (int tt = 0; tt < 4; tt++)
#pragma unroll
            for (int m = 0; m < 4; m++)
                *(uint32_t*)(base + tt * 16 + m * 4) =
                    h2(x[2 * tt + 8 * m], x[2 * tt + 8 * m + 1]);
    }
    __syncthreads();

    // ---- Fill-side constants ----
    const int fc = lid & 7;                 // 16B k-chunk (4 floats)
    const int hl = (lid >> 3) & 1;          // row-pair half (+8)
    const int rr = (lid >> 4) & 1;
    const int rowoff = 2 * w4 + rr + 8 * hl;    // + 16*it
    const uint32_t sts_off = (uint32_t)((fc >> 2) * 2048 +
                             ((2 * w4 + rr) * 4 + 2 * (fc & 1) + hl) * 16 +
                             ((fc >> 1) & 1) * 8);

    char* Ag = smem + SMB_A + gid * 16384;  // 4 buffers of 4096

    // ---- MMA-side constants ----
    const char* aBase = Ag + (g * 4 + t) * 16;
    const char* wBase = smem + SMB_W + (nw >> 3) * 4096 + (g * 4 + t) * 16;
    float* scr = (float*)(smem + SMB_SCR + wid * 4096);   // 32 rows x 32 words
    const int barid = gid + 1;
    const int ntiles = (E + 255) >> 8;

    auto ldg_nf = [&](int base_e, int sub, float* x) {
#pragma unroll
        for (int it = 0; it < 4; it++) {
            int e = base_e + rowoff + 16 * it;
            int eg2 = (e < E) ? e : (E - 1);
            const int s  = ei[eg2];
            const int dd = ei[(size_t)E + eg2];
            const float4 a = *(const float4*)(nf + (size_t)s  * 128 + sub * 32 + fc * 4);
            const float4 b = *(const float4*)(nf + (size_t)dd * 128 + sub * 32 + fc * 4);
            x[4 * it]     = a.x + b.x; x[4 * it + 1] = a.y + b.y;
            x[4 * it + 2] = a.z + b.z; x[4 * it + 3] = a.w + b.w;
        }
    };
    auto ldg_ef = [&](int base_e, int sub, float* x) {
#pragma unroll
        for (int it = 0; it < 4; it++) {
            int e = base_e + rowoff + 16 * it;
            int eg2 = (e < E) ? e : (E - 1);
            const float4 v = *(const float4*)(ef + (size_t)eg2 * 128 + sub * 32 + fc * 4);
            x[4 * it]     = v.x; x[4 * it + 1] = v.y;
            x[4 * it + 2] = v.z; x[4 * it + 3] = v.w;
        }
    };
    auto sts_x = [&](int bsel, const float* x) {
        char* base = Ag + bsel * 4096 + sts_off;
#pragma unroll
        for (int it = 0; it < 4; it++) {
            const uint32_t v0 = h2(x[4 * it], x[4 * it + 1]);
            const uint32_t v1 = h2(x[4 * it + 2], x[4 * it + 3]);
            const uint32_t r0 = __shfl_xor_sync(0xFFFFFFFFu, v0, 8);
            const uint32_t r1 = __shfl_xor_sync(0xFFFFFFFFu, v1, 8);
            const uint2 val = hl ? make_uint2(r1, v1) : make_uint2(v0, r0);
            *(uint2*)(base + it * 512) = val;
        }
    };
    auto mma_sub = [&](int bsel, int p, float (*acc)[4][4]) {
        uint4 bv[4];
#pragma unroll
        for (int j = 0; j < 4; j++)
            bv[j] = *(const uint4*)(wBase + j * 4096 + p * 512);
        const char* ab = aBase + bsel * 4096;
#pragma unroll
        for (int sp = 0; sp < 2; sp++) {
            uint4 av[4];
#pragma unroll
            for (int i = 0; i < 4; i++)
                av[i] = *(const uint4*)(ab + sp * 2048 + i * 512);
#pragma unroll
            for (int i = 0; i < 4; i++)
#pragma unroll
                for (int j = 0; j < 4; j++)
                    mma_f16(acc[i][j], av[i].x, av[i].y, av[i].z, av[i].w,
                            sp ? bv[j].z : bv[j].x, sp ? bv[j].w : bv[j].y);
        }
    };
    auto ldg_seg = [&](int base_e, int seg, float* x) {
        if (seg < 4) ldg_nf(base_e, seg, x);
        else         ldg_ef(base_e, seg - 4, x);
    };

    // ---- Prologue: buf0 <- DATA(0); x <- DATA(1) ----
    int tile = blockIdx.x;
    if (tile >= ntiles) return;
    int e0g = tile * 256 + gid * 64;
    float x[16];
    ldg_nf(e0g, 0, x);
    sts_x(0, x);
    ldg_nf(e0g, 1, x);
    asm volatile("bar.sync %0, 128;" :: "r"(barid) : "memory");

    while (true) {
        float acc[4][4][4] = {};
        const int ntile = tile + gridDim.x;
        const int ne0g  = ntile * 256 + gid * 64;
        const int nbase = (ntile < ntiles) ? ne0g : 0;

        // s = 0..5: sts DATA(s+1); ldg DATA(s+2); mma buf[s&3]
#pragma unroll
        for (int s = 0; s < 6; s++) {
            sts_x((s + 1) & 3, x);
            ldg_seg(e0g, s + 2, x);
            mma_sub(s & 3, s, acc);
            asm volatile("bar.sync %0, 128;" :: "r"(barid) : "memory");
        }
        // s = 6: sts DATA(7); ldg NEXT seg0; mma buf[2]
        sts_x(3, x);
        ldg_nf(nbase, 0, x);
        mma_sub(2, 6, acc);
        asm volatile("bar.sync %0, 128;" :: "r"(barid) : "memory");
        // s = 7: sts NEXT seg0 -> buf0; ldg NEXT seg1; mma buf[3]
        sts_x(0, x);
        ldg_nf(nbase, 1, x);
        mma_sub(3, 7, acc);
        asm volatile("bar.sync %0, 128;" :: "r"(barid) : "memory");

        // ---- Epilogue: bias+relu -> warp-private smem bounce -> STG.128 ----
#pragma unroll 1
        for (int ch = 0; ch < 2; ch++) {
            // STS.64: fragment scatter into rotated layout (stride 32 words)
#pragma unroll
            for (int ii = 0; ii < 2; ii++) {
                const int i = 2 * ch + ii;
#pragma unroll
                for (int h = 0; h < 2; h++) {
                    const int rl = 16 * ii + 8 * h + g;
#pragma unroll
                    for (int j = 0; j < 4; j++) {
                        const int col = nw + 8 * j + 2 * t;
                        float2 v;
                        v.x = fmaxf(acc[i][j][2 * h]     + bsm[col],     0.f);
                        v.y = fmaxf(acc[i][j][2 * h + 1] + bsm[col + 1], 0.f);
                        const int word = rl * 32 +
                            4 * ((2 * j + (t >> 1) + rl) & 7) + 2 * (t & 1);
                        *(float2*)(scr + word) = v;
                    }
                }
            }
            __syncwarp();
            // LDS.128 whole rows + STG.128 full lines
#pragma unroll
            for (int q = 0; q < 8; q++) {
                const int rl = 4 * q + (lid >> 3);
                const int c  = lid & 7;
                const int word = rl * 32 + 4 * ((c + rl) & 7);
                const float4 v = *(const float4*)(scr + word);
                const int r = e0g + 32 * ch + rl;
                if (r < E)
                    *(float4*)(out + (size_t)r * 128 + nw + 4 * c) = v;
            }
            __syncwarp();
        }

        if (ntile >= ntiles) break;
        tile = ntile; e0g = ne0g;
    }
}

extern "C" void kernel_launch(void* const* d_in, const int* in_sizes, int n_in,
                              void* d_out, int out_size) {
    const float* nf = (const float*)d_in[0];
    const int*   ei = (const int*)d_in[1];
    const float* ef = (const float*)d_in[2];
    const float* W  = (const float*)d_in[3];
    const float* b  = (const float*)d_in[4];
    float* out = (float*)d_out;

    const int E = in_sizes[2] / 128;

    cudaFuncSetAttribute(edge_update_kernel,
                         cudaFuncAttributeMaxDynamicSharedMemorySize, SM_BYTES);

    int dev = 0, sms = 148;
    cudaGetDevice(&dev);
    cudaDeviceGetAttribute(&sms, cudaDevAttrMultiProcessorCount, dev);

    const int ntiles = (E + 255) / 256;
    const int grid = (sms < ntiles) ? sms : ntiles;

    edge_update_kernel<<<grid, 512, SM_BYTES>>>(nf, ei, ef, W, b, out, E);
}

// round 15
// speedup vs baseline: 2.1591x; 2.1591x over previous
#include <cuda_runtime.h>
#include <cuda_fp16.h>
#include <cstdint>

// ============================================================================
// EdgeUpdate: out[e] = relu( concat(nf[src[e]]+nf[dst[e]], ef[e]) @ W^T + b )
// GEMM: M=E (640000), N=128, K=256. fp16 mma.m16n8k16, fp32 accumulate.
//
// R15 = R12 pipeline + smem-bounce epilogue at ZERO extra smem:
//   scratch = buf2+buf3 of the group's A ring (dead during epilogue; buf2 is
//   first rewritten at s=1, after the s=0 barrier that post-dates epilogue).
//   smem total = 131584 B (same as R12) -> L1D carveout ~96KB restored
//   (R14's regression was the carveout shrinking to ~31KB, pushing the
//   32x-reuse nf gather from L1 hits to L2: L2 37.6% -> 58.7%).
// Corrected scratch swizzle (rotation 2*rl):
//   word(r, L, u) = r*32 + 4*((L + 2r)&7) + u
//   STS.64 phase banks 4*((2j+t2+2g)&7)+2t1: t2+2g covers 0..7 -> conflict-
//   free; LDS.128 phase = one row = all 32 banks; STG.128 = full lines.
// ============================================================================

static constexpr int SMB_BIAS = 0;
static constexpr int SMB_W    = 512;                  // 64 KB
static constexpr int SMB_A    = 512 + 65536;          // 4 groups x 4 x 4096
static constexpr int SM_BYTES = SMB_A + 4 * 16384;    // 131584 (== R12)

__device__ __forceinline__ void mma_f16(float* d, uint32_t a0, uint32_t a1,
                                        uint32_t a2, uint32_t a3,
                                        uint32_t b0, uint32_t b1) {
    asm volatile(
        "mma.sync.aligned.m16n8k16.row.col.f32.f16.f16.f32 "
        "{%0,%1,%2,%3}, {%4,%5,%6,%7}, {%8,%9}, {%0,%1,%2,%3};"
        : "+f"(d[0]), "+f"(d[1]), "+f"(d[2]), "+f"(d[3])
        : "r"(a0), "r"(a1), "r"(a2), "r"(a3), "r"(b0), "r"(b1));
}

__device__ __forceinline__ uint32_t h2(float lo, float hi) {
    __half2 v = __floats2half2_rn(lo, hi);
    return *reinterpret_cast<uint32_t*>(&v);
}

__global__ void __launch_bounds__(512, 1)
edge_update_kernel(const float* __restrict__ nf,
                   const int* __restrict__ ei,      // int32[2*E] (JAX x64 off)
                   const float* __restrict__ ef,
                   const float* __restrict__ W,
                   const float* __restrict__ bias,
                   float* __restrict__ out, int E) {
    extern __shared__ char smem[];
    float* bsm = (float*)(smem + SMB_BIAS);

    const int tid = threadIdx.x;
    const int wid = tid >> 5;
    const int lid = tid & 31;
    const int g   = lid >> 2;          // 0..7
    const int t   = lid & 3;           // 0..3
    const int gid = wid >> 2;          // group 0..3
    const int w4  = wid & 3;           // warp in group = N strip
    const int nw  = w4 * 32;

    if (tid < 128) bsm[tid] = bias[tid];

    // ---- One-time: W -> packed fp16 smem ----
    for (int task = tid; task < 1024; task += 512) {
        const int c = task >> 3, p = task & 7;
        const float* src = W + c * 256 + p * 32;
        float x[32];
#pragma unroll
        for (int i = 0; i < 8; i++) {
            float4 v = ((const float4*)src)[i];
            x[4 * i] = v.x; x[4 * i + 1] = v.y;
            x[4 * i + 2] = v.z; x[4 * i + 3] = v.w;
        }
        char* base = smem + SMB_W + (c >> 3) * 4096 + p * 512 + (c & 7) * 64;
#pragma unroll
        for (int tt = 0; tt < 4; tt++)
#pragma unroll
            for (int m = 0; m < 4; m++)
                *(uint32_t*)(base + tt * 16 + m * 4) =
                    h2(x[2 * tt + 8 * m], x[2 * tt + 8 * m + 1]);
    }
    __syncthreads();

    // ---- Fill-side constants ----
    const int fc = lid & 7;                 // 16B k-chunk (4 floats)
    const int hl = (lid >> 3) & 1;          // row-pair half (+8)
    const int rr = (lid >> 4) & 1;
    const int rowoff = 2 * w4 + rr + 8 * hl;    // + 16*it
    const uint32_t sts_off = (uint32_t)((fc >> 2) * 2048 +
                             ((2 * w4 + rr) * 4 + 2 * (fc & 1) + hl) * 16 +
                             ((fc >> 1) & 1) * 8);

    char* Ag = smem + SMB_A + gid * 16384;  // 4 buffers of 4096

    // ---- MMA-side constants ----
    const char* aBase = Ag + (g * 4 + t) * 16;
    const char* wBase = smem + SMB_W + (nw >> 3) * 4096 + (g * 4 + t) * 16;
    // epilogue scratch: buf2+buf3 of this group's ring, 2KB per warp
    float* scr = (float*)(Ag + 8192 + w4 * 2048);   // 16 rows x 32 words
    const int barid = gid + 1;
    const int ntiles = (E + 255) >> 8;

    auto ldg_nf = [&](int base_e, int sub, float* x) {
#pragma unroll
        for (int it = 0; it < 4; it++) {
            int e = base_e + rowoff + 16 * it;
            int eg2 = (e < E) ? e : (E - 1);
            const int s  = ei[eg2];
            const int dd = ei[(size_t)E + eg2];
            const float4 a = *(const float4*)(nf + (size_t)s  * 128 + sub * 32 + fc * 4);
            const float4 b = *(const float4*)(nf + (size_t)dd * 128 + sub * 32 + fc * 4);
            x[4 * it]     = a.x + b.x; x[4 * it + 1] = a.y + b.y;
            x[4 * it + 2] = a.z + b.z; x[4 * it + 3] = a.w + b.w;
        }
    };
    auto ldg_ef = [&](int base_e, int sub, float* x) {
#pragma unroll
        for (int it = 0; it < 4; it++) {
            int e = base_e + rowoff + 16 * it;
            int eg2 = (e < E) ? e : (E - 1);
            const float4 v = *(const float4*)(ef + (size_t)eg2 * 128 + sub * 32 + fc * 4);
            x[4 * it]     = v.x; x[4 * it + 1] = v.y;
            x[4 * it + 2] = v.z; x[4 * it + 3] = v.w;
        }
    };
    auto sts_x = [&](int bsel, const float* x) {
        char* base = Ag + bsel * 4096 + sts_off;
#pragma unroll
        for (int it = 0; it < 4; it++) {
            const uint32_t v0 = h2(x[4 * it], x[4 * it + 1]);
            const uint32_t v1 = h2(x[4 * it + 2], x[4 * it + 3]);
            const uint32_t r0 = __shfl_xor_sync(0xFFFFFFFFu, v0, 8);
            const uint32_t r1 = __shfl_xor_sync(0xFFFFFFFFu, v1, 8);
            const uint2 val = hl ? make_uint2(r1, v1) : make_uint2(v0, r0);
            *(uint2*)(base + it * 512) = val;
        }
    };
    auto mma_sub = [&](int bsel, int p, float (*acc)[4][4]) {
        uint4 bv[4];
#pragma unroll
        for (int j = 0; j < 4; j++)
            bv[j] = *(const uint4*)(wBase + j * 4096 + p * 512);
        const char* ab = aBase + bsel * 4096;
#pragma unroll
        for (int sp = 0; sp < 2; sp++) {
            uint4 av[4];
#pragma unroll
            for (int i = 0; i < 4; i++)
                av[i] = *(const uint4*)(ab + sp * 2048 + i * 512);
#pragma unroll
            for (int i = 0; i < 4; i++)
#pragma unroll
                for (int j = 0; j < 4; j++)
                    mma_f16(acc[i][j], av[i].x, av[i].y, av[i].z, av[i].w,
                            sp ? bv[j].z : bv[j].x, sp ? bv[j].w : bv[j].y);
        }
    };
    auto ldg_seg = [&](int base_e, int seg, float* x) {
        if (seg < 4) ldg_nf(base_e, seg, x);
        else         ldg_ef(base_e, seg - 4, x);
    };

    // ---- Prologue: buf0 <- DATA(0); x <- DATA(1) ----
    int tile = blockIdx.x;
    if (tile >= ntiles) return;
    int e0g = tile * 256 + gid * 64;
    float x[16];
    ldg_nf(e0g, 0, x);
    sts_x(0, x);
    ldg_nf(e0g, 1, x);
    asm volatile("bar.sync %0, 128;" :: "r"(barid) : "memory");

    while (true) {
        float acc[4][4][4] = {};
        const int ntile = tile + gridDim.x;
        const int ne0g  = ntile * 256 + gid * 64;
        const int nbase = (ntile < ntiles) ? ne0g : 0;

        // s = 0..5: sts DATA(s+1); ldg DATA(s+2); mma buf[s&3]
#pragma unroll
        for (int s = 0; s < 6; s++) {
            sts_x((s + 1) & 3, x);
            ldg_seg(e0g, s + 2, x);
            mma_sub(s & 3, s, acc);
            asm volatile("bar.sync %0, 128;" :: "r"(barid) : "memory");
        }
        // s = 6: sts DATA(7); ldg NEXT seg0; mma buf[2]
        sts_x(3, x);
        ldg_nf(nbase, 0, x);
        mma_sub(2, 6, acc);
        asm volatile("bar.sync %0, 128;" :: "r"(barid) : "memory");
        // s = 7: sts NEXT seg0 -> buf0; ldg NEXT seg1; mma buf[3]
        sts_x(0, x);
        ldg_nf(nbase, 1, x);
        mma_sub(3, 7, acc);
        asm volatile("bar.sync %0, 128;" :: "r"(barid) : "memory");

        // ---- Epilogue: bias+relu -> bounce via ring scratch -> STG.128 ----
        // buf2/buf3 are dead here (buf2 first rewritten at next s=1, which is
        // after the s=0 barrier all warps can only reach post-epilogue).
#pragma unroll
        for (int cc = 0; cc < 4; cc++) {
#pragma unroll
            for (int h = 0; h < 2; h++) {
                const int rl = 8 * h + g;
#pragma unroll
                for (int j = 0; j < 4; j++) {
                    const int col = nw + 8 * j + 2 * t;
                    float2 v;
                    v.x = fmaxf(acc[cc][j][2 * h]     + bsm[col],     0.f);
                    v.y = fmaxf(acc[cc][j][2 * h + 1] + bsm[col + 1], 0.f);
                    const int word = rl * 32 +
                        4 * ((2 * j + (t >> 1) + 2 * rl) & 7) + 2 * (t & 1);
                    *(float2*)(scr + word) = v;
                }
            }
            __syncwarp();
#pragma unroll
            for (int q = 0; q < 4; q++) {
                const int rl = 4 * q + (lid >> 3);
                const int c  = lid & 7;
                const int word = rl * 32 + 4 * ((c + 2 * rl) & 7);
                const float4 v = *(const float4*)(scr + word);
                const int r = e0g + 16 * cc + rl;
                if (r < E)
                    *(float4*)(out + (size_t)r * 128 + nw + 4 * c) = v;
            }
            __syncwarp();
        }

        if (ntile >= ntiles) break;
        tile = ntile; e0g = ne0g;
    }
}

extern "C" void kernel_launch(void* const* d_in, const int* in_sizes, int n_in,
                              void* d_out, int out_size) {
    const float* nf = (const float*)d_in[0];
    const int*   ei = (const int*)d_in[1];
    const float* ef = (const float*)d_in[2];
    const float* W  = (const float*)d_in[3];
    const float* b  = (const float*)d_in[4];
    float* out = (float*)d_out;

    const int E = in_sizes[2] / 128;

    cudaFuncSetAttribute(edge_update_kernel,
                         cudaFuncAttributeMaxDynamicSharedMemorySize, SM_BYTES);

    int dev = 0, sms = 148;
    cudaGetDevice(&dev);
    cudaDeviceGetAttribute(&sms, cudaDevAttrMultiProcessorCount, dev);

    const int ntiles = (E + 255) / 256;
    const int grid = (sms < ntiles) ? sms : ntiles;

    edge_update_kernel<<<grid, 512, SM_BYTES>>>(nf, ei, ef, W, b, out, E);
}

// round 16
// speedup vs baseline: 2.1996x; 1.0188x over previous
#include <cuda_runtime.h>
#include <cuda_fp16.h>
#include <cstdint>

// ============================================================================
// EdgeUpdate: out[e] = relu( concat(nf[src[e]]+nf[dst[e]], ef[e]) @ W^T + b )
// GEMM: M=E (640000), N=128, K=256. fp16 mma.m16n8k16, fp32 accumulate.
//
// R16 = R15 with the segment reordered {sts;ldg;mma;bar} -> {mma;sts;ldg;bar}.
// The sts consumes x loaded one segment earlier; when that load runs long
// (ef from DRAM) the old order stalled the segment head, blocking the fully
// data-ready mma behind it. New order: elapsed = max(T_mma, T_x) instead of
// T_x + T_mma. Sync unchanged: sts still precedes the bar that publishes it;
// mma reads buf[s&3], sts writes buf[(s+1)&3] (disjoint); epilogue scratch
// (buf2+buf3) still dead until the post-epilogue s=0 bar.
// Everything else identical to R15 (217us, rel_err 2.78e-4).
// ============================================================================

static constexpr int SMB_BIAS = 0;
static constexpr int SMB_W    = 512;                  // 64 KB
static constexpr int SMB_A    = 512 + 65536;          // 4 groups x 4 x 4096
static constexpr int SM_BYTES = SMB_A + 4 * 16384;    // 131584

__device__ __forceinline__ void mma_f16(float* d, uint32_t a0, uint32_t a1,
                                        uint32_t a2, uint32_t a3,
                                        uint32_t b0, uint32_t b1) {
    asm volatile(
        "mma.sync.aligned.m16n8k16.row.col.f32.f16.f16.f32 "
        "{%0,%1,%2,%3}, {%4,%5,%6,%7}, {%8,%9}, {%0,%1,%2,%3};"
        : "+f"(d[0]), "+f"(d[1]), "+f"(d[2]), "+f"(d[3])
        : "r"(a0), "r"(a1), "r"(a2), "r"(a3), "r"(b0), "r"(b1));
}

__device__ __forceinline__ uint32_t h2(float lo, float hi) {
    __half2 v = __floats2half2_rn(lo, hi);
    return *reinterpret_cast<uint32_t*>(&v);
}

__global__ void __launch_bounds__(512, 1)
edge_update_kernel(const float* __restrict__ nf,
                   const int* __restrict__ ei,      // int32[2*E] (JAX x64 off)
                   const float* __restrict__ ef,
                   const float* __restrict__ W,
                   const float* __restrict__ bias,
                   float* __restrict__ out, int E) {
    extern __shared__ char smem[];
    float* bsm = (float*)(smem + SMB_BIAS);

    const int tid = threadIdx.x;
    const int wid = tid >> 5;
    const int lid = tid & 31;
    const int g   = lid >> 2;          // 0..7
    const int t   = lid & 3;           // 0..3
    const int gid = wid >> 2;          // group 0..3
    const int w4  = wid & 3;           // warp in group = N strip
    const int nw  = w4 * 32;

    if (tid < 128) bsm[tid] = bias[tid];

    // ---- One-time: W -> packed fp16 smem ----
    for (int task = tid; task < 1024; task += 512) {
        const int c = task >> 3, p = task & 7;
        const float* src = W + c * 256 + p * 32;
        float x[32];
#pragma unroll
        for (int i = 0; i < 8; i++) {
            float4 v = ((const float4*)src)[i];
            x[4 * i] = v.x; x[4 * i + 1] = v.y;
            x[4 * i + 2] = v.z; x[4 * i + 3] = v.w;
        }
        char* base = smem + SMB_W + (c >> 3) * 4096 + p * 512 + (c & 7) * 64;
#pragma unroll
        for (int tt = 0; tt < 4; tt++)
#pragma unroll
            for (int m = 0; m < 4; m++)
                *(uint32_t*)(base + tt * 16 + m * 4) =
                    h2(x[2 * tt + 8 * m], x[2 * tt + 8 * m + 1]);
    }
    __syncthreads();

    // ---- Fill-side constants ----
    const int fc = lid & 7;                 // 16B k-chunk (4 floats)
    const int hl = (lid >> 3) & 1;          // row-pair half (+8)
    const int rr = (lid >> 4) & 1;
    const int rowoff = 2 * w4 + rr + 8 * hl;    // + 16*it
    const uint32_t sts_off = (uint32_t)((fc >> 2) * 2048 +
                             ((2 * w4 + rr) * 4 + 2 * (fc & 1) + hl) * 16 +
                             ((fc >> 1) & 1) * 8);

    char* Ag = smem + SMB_A + gid * 16384;  // 4 buffers of 4096

    // ---- MMA-side constants ----
    const char* aBase = Ag + (g * 4 + t) * 16;
    const char* wBase = smem + SMB_W + (nw >> 3) * 4096 + (g * 4 + t) * 16;
    // epilogue scratch: buf2+buf3 of this group's ring, 2KB per warp
    float* scr = (float*)(Ag + 8192 + w4 * 2048);   // 16 rows x 32 words
    const int barid = gid + 1;
    const int ntiles = (E + 255) >> 8;

    auto ldg_nf = [&](int base_e, int sub, float* x) {
#pragma unroll
        for (int it = 0; it < 4; it++) {
            int e = base_e + rowoff + 16 * it;
            int eg2 = (e < E) ? e : (E - 1);
            const int s  = ei[eg2];
            const int dd = ei[(size_t)E + eg2];
            const float4 a = *(const float4*)(nf + (size_t)s  * 128 + sub * 32 + fc * 4);
            const float4 b = *(const float4*)(nf + (size_t)dd * 128 + sub * 32 + fc * 4);
            x[4 * it]     = a.x + b.x; x[4 * it + 1] = a.y + b.y;
            x[4 * it + 2] = a.z + b.z; x[4 * it + 3] = a.w + b.w;
        }
    };
    auto ldg_ef = [&](int base_e, int sub, float* x) {
#pragma unroll
        for (int it = 0; it < 4; it++) {
            int e = base_e + rowoff + 16 * it;
            int eg2 = (e < E) ? e : (E - 1);
            const float4 v = *(const float4*)(ef + (size_t)eg2 * 128 + sub * 32 + fc * 4);
            x[4 * it]     = v.x; x[4 * it + 1] = v.y;
            x[4 * it + 2] = v.z; x[4 * it + 3] = v.w;
        }
    };
    auto sts_x = [&](int bsel, const float* x) {
        char* base = Ag + bsel * 4096 + sts_off;
#pragma unroll
        for (int it = 0; it < 4; it++) {
            const uint32_t v0 = h2(x[4 * it], x[4 * it + 1]);
            const uint32_t v1 = h2(x[4 * it + 2], x[4 * it + 3]);
            const uint32_t r0 = __shfl_xor_sync(0xFFFFFFFFu, v0, 8);
            const uint32_t r1 = __shfl_xor_sync(0xFFFFFFFFu, v1, 8);
            const uint2 val = hl ? make_uint2(r1, v1) : make_uint2(v0, r0);
            *(uint2*)(base + it * 512) = val;
        }
    };
    auto mma_sub = [&](int bsel, int p, float (*acc)[4][4]) {
        uint4 bv[4];
#pragma unroll
        for (int j = 0; j < 4; j++)
            bv[j] = *(const uint4*)(wBase + j * 4096 + p * 512);
        const char* ab = aBase + bsel * 4096;
#pragma unroll
        for (int sp = 0; sp < 2; sp++) {
            uint4 av[4];
#pragma unroll
            for (int i = 0; i < 4; i++)
                av[i] = *(const uint4*)(ab + sp * 2048 + i * 512);
#pragma unroll
            for (int i = 0; i < 4; i++)
#pragma unroll
                for (int j = 0; j < 4; j++)
                    mma_f16(acc[i][j], av[i].x, av[i].y, av[i].z, av[i].w,
                            sp ? bv[j].z : bv[j].x, sp ? bv[j].w : bv[j].y);
        }
    };
    auto ldg_seg = [&](int base_e, int seg, float* x) {
        if (seg < 4) ldg_nf(base_e, seg, x);
        else         ldg_ef(base_e, seg - 4, x);
    };

    // ---- Prologue: buf0 <- DATA(0); x <- DATA(1) ----
    int tile = blockIdx.x;
    if (tile >= ntiles) return;
    int e0g = tile * 256 + gid * 64;
    float x[16];
    ldg_nf(e0g, 0, x);
    sts_x(0, x);
    ldg_nf(e0g, 1, x);
    asm volatile("bar.sync %0, 128;" :: "r"(barid) : "memory");

    while (true) {
        float acc[4][4][4] = {};
        const int ntile = tile + gridDim.x;
        const int ne0g  = ntile * 256 + gid * 64;
        const int nbase = (ntile < ntiles) ? ne0g : 0;

        // s = 0..5: mma buf[s&3]; sts DATA(s+1); ldg DATA(s+2)
#pragma unroll
        for (int s = 0; s < 6; s++) {
            mma_sub(s & 3, s, acc);
            sts_x((s + 1) & 3, x);
            ldg_seg(e0g, s + 2, x);
            asm volatile("bar.sync %0, 128;" :: "r"(barid) : "memory");
        }
        // s = 6: mma buf[2]; sts DATA(7); ldg NEXT seg0
        mma_sub(2, 6, acc);
        sts_x(3, x);
        ldg_nf(nbase, 0, x);
        asm volatile("bar.sync %0, 128;" :: "r"(barid) : "memory");
        // s = 7: mma buf[3]; sts NEXT seg0 -> buf0; ldg NEXT seg1
        mma_sub(3, 7, acc);
        sts_x(0, x);
        ldg_nf(nbase, 1, x);
        asm volatile("bar.sync %0, 128;" :: "r"(barid) : "memory");

        // ---- Epilogue: bias+relu -> bounce via ring scratch -> STG.128 ----
        // buf2/buf3 dead here (buf2 first rewritten at next s=1, after the
        // s=0 barrier that all warps only reach post-epilogue).
#pragma unroll
        for (int cc = 0; cc < 4; cc++) {
#pragma unroll
            for (int h = 0; h < 2; h++) {
                const int rl = 8 * h + g;
#pragma unroll
                for (int j = 0; j < 4; j++) {
                    const int col = nw + 8 * j + 2 * t;
                    float2 v;
                    v.x = fmaxf(acc[cc][j][2 * h]     + bsm[col],     0.f);
                    v.y = fmaxf(acc[cc][j][2 * h + 1] + bsm[col + 1], 0.f);
                    const int word = rl * 32 +
                        4 * ((2 * j + (t >> 1) + 2 * rl) & 7) + 2 * (t & 1);
                    *(float2*)(scr + word) = v;
                }
            }
            __syncwarp();
#pragma unroll
            for (int q = 0; q < 4; q++) {
                const int rl = 4 * q + (lid >> 3);
                const int c  = lid & 7;
                const int word = rl * 32 + 4 * ((c + 2 * rl) & 7);
                const float4 v = *(const float4*)(scr + word);
                const int r = e0g + 16 * cc + rl;
                if (r < E)
                    *(float4*)(out + (size_t)r * 128 + nw + 4 * c) = v;
            }
            __syncwarp();
        }

        if (ntile >= ntiles) break;
        tile = ntile; e0g = ne0g;
    }
}

extern "C" void kernel_launch(void* const* d_in, const int* in_sizes, int n_in,
                              void* d_out, int out_size) {
    const float* nf = (const float*)d_in[0];
    const int*   ei = (const int*)d_in[1];
    const float* ef = (const float*)d_in[2];
    const float* W  = (const float*)d_in[3];
    const float* b  = (const float*)d_in[4];
    float* out = (float*)d_out;

    const int E = in_sizes[2] / 128;

    cudaFuncSetAttribute(edge_update_kernel,
                         cudaFuncAttributeMaxDynamicSharedMemorySize, SM_BYTES);

    int dev = 0, sms = 148;
    cudaGetDevice(&dev);
    cudaDeviceGetAttribute(&sms, cudaDevAttrMultiProcessorCount, dev);

    const int ntiles = (E + 255) / 256;
    const int grid = (sms < ntiles) ? sms : ntiles;

    edge_update_kernel<<<grid, 512, SM_BYTES>>>(nf, ei, ef, W, b, out, E);
}

// round 17
// speedup vs baseline: 2.2554x; 1.0254x over previous
#include <cuda_runtime.h>
#include <cuda_fp16.h>
#include <cstdint>

// ============================================================================
// EdgeUpdate: out[e] = relu( concat(nf[src[e]]+nf[dst[e]], ef[e]) @ W^T + b )
// GEMM: M=E (640000), N=128, K=256. fp16 mma.m16n8k16, fp32 accumulate.
//
// R17 = R16 with paired segments: one group-barrier per TWO 32-k sub-phases
// (4 interval bars + 1 epilogue bar = 5 bars/tile, was 8). Single x staging
// preserved by storing at ring distance 2:
//   interval u: mma buf[2u]; sts x=data(2u+2)->buf[2u+2]; ldg data(2u+3);
//               mma buf[2u+1]; sts data(2u+3)->buf[2u+3]; ldg data(2u+4); bar
// Ring check: interval u reads bufs {2u,2u+1}, writes {2u+2,2u+3} (mod 4) --
// disjoint; cross-interval protected by the bar. Epilogue scratch = buf2/3
// (last read = u3's mma), guarded from next-tile u0's sts by the post-
// epilogue bar. Everything else identical to R16 (213us, rel_err 2.78e-4).
// ============================================================================

static constexpr int SMB_BIAS = 0;
static constexpr int SMB_W    = 512;                  // 64 KB
static constexpr int SMB_A    = 512 + 65536;          // 4 groups x 4 x 4096
static constexpr int SM_BYTES = SMB_A + 4 * 16384;    // 131584

__device__ __forceinline__ void mma_f16(float* d, uint32_t a0, uint32_t a1,
                                        uint32_t a2, uint32_t a3,
                                        uint32_t b0, uint32_t b1) {
    asm volatile(
        "mma.sync.aligned.m16n8k16.row.col.f32.f16.f16.f32 "
        "{%0,%1,%2,%3}, {%4,%5,%6,%7}, {%8,%9}, {%0,%1,%2,%3};"
        : "+f"(d[0]), "+f"(d[1]), "+f"(d[2]), "+f"(d[3])
        : "r"(a0), "r"(a1), "r"(a2), "r"(a3), "r"(b0), "r"(b1));
}

__device__ __forceinline__ uint32_t h2(float lo, float hi) {
    __half2 v = __floats2half2_rn(lo, hi);
    return *reinterpret_cast<uint32_t*>(&v);
}

__global__ void __launch_bounds__(512, 1)
edge_update_kernel(const float* __restrict__ nf,
                   const int* __restrict__ ei,      // int32[2*E] (JAX x64 off)
                   const float* __restrict__ ef,
                   const float* __restrict__ W,
                   const float* __restrict__ bias,
                   float* __restrict__ out, int E) {
    extern __shared__ char smem[];
    float* bsm = (float*)(smem + SMB_BIAS);

    const int tid = threadIdx.x;
    const int wid = tid >> 5;
    const int lid = tid & 31;
    const int g   = lid >> 2;          // 0..7
    const int t   = lid & 3;           // 0..3
    const int gid = wid >> 2;          // group 0..3
    const int w4  = wid & 3;           // warp in group = N strip
    const int nw  = w4 * 32;

    if (tid < 128) bsm[tid] = bias[tid];

    // ---- One-time: W -> packed fp16 smem ----
    for (int task = tid; task < 1024; task += 512) {
        const int c = task >> 3, p = task & 7;
        const float* src = W + c * 256 + p * 32;
        float x[32];
#pragma unroll
        for (int i = 0; i < 8; i++) {
            float4 v = ((const float4*)src)[i];
            x[4 * i] = v.x; x[4 * i + 1] = v.y;
            x[4 * i + 2] = v.z; x[4 * i + 3] = v.w;
        }
        char* base = smem + SMB_W + (c >> 3) * 4096 + p * 512 + (c & 7) * 64;
#pragma unroll
        for (int tt = 0; tt < 4; tt++)
#pragma unroll
            for (int m = 0; m < 4; m++)
                *(uint32_t*)(base + tt * 16 + m * 4) =
                    h2(x[2 * tt + 8 * m], x[2 * tt + 8 * m + 1]);
    }
    __syncthreads();

    // ---- Fill-side constants ----
    const int fc = lid & 7;                 // 16B k-chunk (4 floats)
    const int hl = (lid >> 3) & 1;          // row-pair half (+8)
    const int rr = (lid >> 4) & 1;
    const int rowoff = 2 * w4 + rr + 8 * hl;    // + 16*it
    const uint32_t sts_off = (uint32_t)((fc >> 2) * 2048 +
                             ((2 * w4 + rr) * 4 + 2 * (fc & 1) + hl) * 16 +
                             ((fc >> 1) & 1) * 8);

    char* Ag = smem + SMB_A + gid * 16384;  // 4 buffers of 4096

    // ---- MMA-side constants ----
    const char* aBase = Ag + (g * 4 + t) * 16;
    const char* wBase = smem + SMB_W + (nw >> 3) * 4096 + (g * 4 + t) * 16;
    // epilogue scratch: buf2+buf3 of this group's ring, 2KB per warp
    float* scr = (float*)(Ag + 8192 + w4 * 2048);   // 16 rows x 32 words
    const int barid = gid + 1;
    const int ntiles = (E + 255) >> 8;

    auto ldg_nf = [&](int base_e, int sub, float* x) {
#pragma unroll
        for (int it = 0; it < 4; it++) {
            int e = base_e + rowoff + 16 * it;
            int eg2 = (e < E) ? e : (E - 1);
            const int s  = ei[eg2];
            const int dd = ei[(size_t)E + eg2];
            const float4 a = *(const float4*)(nf + (size_t)s  * 128 + sub * 32 + fc * 4);
            const float4 b = *(const float4*)(nf + (size_t)dd * 128 + sub * 32 + fc * 4);
            x[4 * it]     = a.x + b.x; x[4 * it + 1] = a.y + b.y;
            x[4 * it + 2] = a.z + b.z; x[4 * it + 3] = a.w + b.w;
        }
    };
    auto ldg_ef = [&](int base_e, int sub, float* x) {
#pragma unroll
        for (int it = 0; it < 4; it++) {
            int e = base_e + rowoff + 16 * it;
            int eg2 = (e < E) ? e : (E - 1);
            const float4 v = *(const float4*)(ef + (size_t)eg2 * 128 + sub * 32 + fc * 4);
            x[4 * it]     = v.x; x[4 * it + 1] = v.y;
            x[4 * it + 2] = v.z; x[4 * it + 3] = v.w;
        }
    };
    auto sts_x = [&](int bsel, const float* x) {
        char* base = Ag + bsel * 4096 + sts_off;
#pragma unroll
        for (int it = 0; it < 4; it++) {
            const uint32_t v0 = h2(x[4 * it], x[4 * it + 1]);
            const uint32_t v1 = h2(x[4 * it + 2], x[4 * it + 3]);
            const uint32_t r0 = __shfl_xor_sync(0xFFFFFFFFu, v0, 8);
            const uint32_t r1 = __shfl_xor_sync(0xFFFFFFFFu, v1, 8);
            const uint2 val = hl ? make_uint2(r1, v1) : make_uint2(v0, r0);
            *(uint2*)(base + it * 512) = val;
        }
    };
    auto mma_sub = [&](int bsel, int p, float (*acc)[4][4]) {
        uint4 bv[4];
#pragma unroll
        for (int j = 0; j < 4; j++)
            bv[j] = *(const uint4*)(wBase + j * 4096 + p * 512);
        const char* ab = aBase + bsel * 4096;
#pragma unroll
        for (int sp = 0; sp < 2; sp++) {
            uint4 av[4];
#pragma unroll
            for (int i = 0; i < 4; i++)
                av[i] = *(const uint4*)(ab + sp * 2048 + i * 512);
#pragma unroll
            for (int i = 0; i < 4; i++)
#pragma unroll
                for (int j = 0; j < 4; j++)
                    mma_f16(acc[i][j], av[i].x, av[i].y, av[i].z, av[i].w,
                            sp ? bv[j].z : bv[j].x, sp ? bv[j].w : bv[j].y);
        }
    };
    // data(s): s 0..3 = this tile nf sub s; 4..7 = this tile ef sub s-4;
    //          8..10 = NEXT tile nf sub s-8
    auto ldg_data = [&](int s, int e0g_, int nbase_, float* x) {
        if (s < 4)      ldg_nf(e0g_, s, x);
        else if (s < 8) ldg_ef(e0g_, s - 4, x);
        else            ldg_nf(nbase_, s - 8, x);
    };

    // ---- Prologue: buf0 <- data0; buf1 <- data1; x <- data2 ----
    int tile = blockIdx.x;
    if (tile >= ntiles) return;
    int e0g = tile * 256 + gid * 64;
    float x[16];
    ldg_nf(e0g, 0, x); sts_x(0, x);
    ldg_nf(e0g, 1, x); sts_x(1, x);
    ldg_nf(e0g, 2, x);
    asm volatile("bar.sync %0, 128;" :: "r"(barid) : "memory");

    while (true) {
        float acc[4][4][4] = {};
        const int ntile = tile + gridDim.x;
        const int ne0g  = ntile * 256 + gid * 64;
        const int nbase = (ntile < ntiles) ? ne0g : 0;

        // 4 paired intervals, one bar each
#pragma unroll
        for (int u = 0; u < 4; u++) {
            mma_sub((2 * u) & 3, 2 * u, acc);
            sts_x((2 * u + 2) & 3, x);
            ldg_data(2 * u + 3, e0g, nbase, x);
            mma_sub((2 * u + 1) & 3, 2 * u + 1, acc);
            sts_x((2 * u + 3) & 3, x);
            ldg_data(2 * u + 4, e0g, nbase, x);
            asm volatile("bar.sync %0, 128;" :: "r"(barid) : "memory");
        }

        // ---- Epilogue: bias+relu -> bounce via ring scratch -> STG.128 ----
        // buf2/3 dead here (last read = u3's mma, before u3's bar); next
        // write to buf2/3 is next-tile u0's sts, guarded by the bar below.
#pragma unroll
        for (int cc = 0; cc < 4; cc++) {
#pragma unroll
            for (int h = 0; h < 2; h++) {
                const int rl = 8 * h + g;
#pragma unroll
                for (int j = 0; j < 4; j++) {
                    const int col = nw + 8 * j + 2 * t;
                    float2 v;
                    v.x = fmaxf(acc[cc][j][2 * h]     + bsm[col],     0.f);
                    v.y = fmaxf(acc[cc][j][2 * h + 1] + bsm[col + 1], 0.f);
                    const int word = rl * 32 +
                        4 * ((2 * j + (t >> 1) + 2 * rl) & 7) + 2 * (t & 1);
                    *(float2*)(scr + word) = v;
                }
            }
            __syncwarp();
#pragma unroll
            for (int q = 0; q < 4; q++) {
                const int rl = 4 * q + (lid >> 3);
                const int c  = lid & 7;
                const int word = rl * 32 + 4 * ((c + 2 * rl) & 7);
                const float4 v = *(const float4*)(scr + word);
                const int r = e0g + 16 * cc + rl;
                if (r < E)
                    *(float4*)(out + (size_t)r * 128 + nw + 4 * c) = v;
            }
            __syncwarp();
        }
        asm volatile("bar.sync %0, 128;" :: "r"(barid) : "memory");

        if (ntile >= ntiles) break;
        tile = ntile; e0g = ne0g;
    }
}

extern "C" void kernel_launch(void* const* d_in, const int* in_sizes, int n_in,
                              void* d_out, int out_size) {
    const float* nf = (const float*)d_in[0];
    const int*   ei = (const int*)d_in[1];
    const float* ef = (const float*)d_in[2];
    const float* W  = (const float*)d_in[3];
    const float* b  = (const float*)d_in[4];
    float* out = (float*)d_out;

    const int E = in_sizes[2] / 128;

    cudaFuncSetAttribute(edge_update_kernel,
                         cudaFuncAttributeMaxDynamicSharedMemorySize, SM_BYTES);

    int dev = 0, sms = 148;
    cudaGetDevice(&dev);
    cudaDeviceGetAttribute(&sms, cudaDevAttrMultiProcessorCount, dev);

    const int ntiles = (E + 255) / 256;
    const int grid = (sms < ntiles) ? sms : ntiles;

    edge_update_kernel<<<grid, 512, SM_BYTES>>>(nf, ei, ef, W, b, out, E);
}